// round 4
// baseline (speedup 1.0000x reference)
#include <cuda_runtime.h>

#define N_NODES 16384
#define NHID    128
#define NEDGE   524288
#define EDIM    16
#define NHID2   256
#define BN_EPS  1e-5f
#define NSLOPE  0.01f
#define ROWCAP  256

// ---------------- scratch (static __device__ per allocation rules) ----------
static __device__ float g_Q[N_NODES * NHID];
static __device__ float g_K[N_NODES * NHID];
static __device__ float g_V[N_NODES * NHID];
static __device__ float g_SV[NHID];
static __device__ float g_escore[NEDGE];          // per-edge leaky score
static __device__ int   g_cnt[N_NODES];
static __device__ int   g_rowstart[N_NODES + 1];
static __device__ int   g_cursor[N_NODES];
static __device__ int   g_sdst[NEDGE];            // CSR dst
static __device__ float g_sw[NEDGE];              // CSR score
static __device__ float g_h1[N_NODES * NHID];     // x + x_new (pre-BN1)
static __device__ float g_mid[N_NODES * NHID2];   // relu(bn1(h1)@W1+b1)
static __device__ float g_z[N_NODES * NHID];      // h + ffn (pre-BN2)
static __device__ float g_s1[NHID], g_ss1[NHID], g_s2[NHID], g_ss2[NHID];
static __device__ int   g_is64;

// ---------------- helpers ---------------------------------------------------
__device__ __forceinline__ int edge_val(const void* ei, int is64, int row, int e) {
    if (is64) return (int)((const long long*)ei)[(size_t)row * NEDGE + e];
    return ((const int*)ei)[(size_t)row * NEDGE + e];
}

// ---------------- init: zero accumulators + edge dtype probe ----------------
__global__ void init_kernel(const void* __restrict__ ei) {
    int idx = blockIdx.x * 256 + threadIdx.x;
    if (idx < N_NODES) g_cnt[idx] = 0;
    if (idx < NHID) {
        g_SV[idx] = 0.f;
        g_s1[idx] = 0.f; g_ss1[idx] = 0.f;
        g_s2[idx] = 0.f; g_ss2[idx] = 0.f;
    }
    if (idx == 0) {
        // int64 little-endian: high words of small nonneg values are all 0.
        const int* p = (const int*)ei;
        int nz = 0;
        for (int i = 0; i < 64; i++) nz |= p[2 * i + 1];
        g_is64 = (nz == 0) ? 1 : 0;
    }
}

// ---------------- QKV GEMM: 128x128 tile, 8x8 regs, fp32 --------------------
// V branch additionally reduces per-column sums into g_SV (fused sv_kernel).
__global__ void __launch_bounds__(256) qkv_kernel(
    const float* __restrict__ x,
    const float* __restrict__ Wq, const float* __restrict__ bq,
    const float* __restrict__ Wk, const float* __restrict__ bk,
    const float* __restrict__ Wv, const float* __restrict__ bv) {
    __shared__ float sA[128][33];
    __shared__ float sB[32][128];
    const float* W; const float* bias; float* out;
    if (blockIdx.y == 0)      { W = Wq; bias = bq; out = g_Q; }
    else if (blockIdx.y == 1) { W = Wk; bias = bk; out = g_K; }
    else                      { W = Wv; bias = bv; out = g_V; }

    int tid = threadIdx.x;
    int tx = tid & 15, ty = tid >> 4;
    int row0 = blockIdx.x * 128;

    float acc[8][8];
#pragma unroll
    for (int r = 0; r < 8; r++)
#pragma unroll
        for (int j = 0; j < 8; j++) acc[r][j] = 0.f;

    for (int k0 = 0; k0 < NHID; k0 += 32) {
#pragma unroll
        for (int i = tid; i < 1024; i += 256) {           // A tile 128x32
            int r = i >> 3, c = (i & 7) << 2;
            float4 v = *(const float4*)(x + (size_t)(row0 + r) * NHID + k0 + c);
            sA[r][c] = v.x; sA[r][c + 1] = v.y; sA[r][c + 2] = v.z; sA[r][c + 3] = v.w;
        }
#pragma unroll
        for (int i = tid; i < 1024; i += 256) {           // B tile 32x128
            int r = i >> 5, c = (i & 31) << 2;
            *(float4*)&sB[r][c] = *(const float4*)(W + (size_t)(k0 + r) * NHID + c);
        }
        __syncthreads();
#pragma unroll
        for (int k = 0; k < 32; k++) {
            float a[8], b[8];
#pragma unroll
            for (int r = 0; r < 8; r++) a[r] = sA[ty * 8 + r][k];
            float4 b0 = *(const float4*)&sB[k][tx * 8];
            float4 b1 = *(const float4*)&sB[k][tx * 8 + 4];
            b[0] = b0.x; b[1] = b0.y; b[2] = b0.z; b[3] = b0.w;
            b[4] = b1.x; b[5] = b1.y; b[6] = b1.z; b[7] = b1.w;
#pragma unroll
            for (int r = 0; r < 8; r++)
#pragma unroll
                for (int j = 0; j < 8; j++) acc[r][j] = fmaf(a[r], b[j], acc[r][j]);
        }
        __syncthreads();
    }
    float bb[8];
#pragma unroll
    for (int j = 0; j < 8; j++) bb[j] = bias[tx * 8 + j];
    float colsum[8];
#pragma unroll
    for (int j = 0; j < 8; j++) colsum[j] = 0.f;
#pragma unroll
    for (int r = 0; r < 8; r++) {
        float* o = out + (size_t)(row0 + ty * 8 + r) * NHID + tx * 8;
        float v[8];
#pragma unroll
        for (int j = 0; j < 8; j++) { v[j] = acc[r][j] + bb[j]; colsum[j] += v[j]; }
        *(float4*)o = make_float4(v[0], v[1], v[2], v[3]);
        *(float4*)(o + 4) = make_float4(v[4], v[5], v[6], v[7]);
    }
    if (blockIdx.y == 2) {
        // fused column-sum of V: partials via reused sA, one atomic per column
        float* red = &sA[0][0];                 // 16*128 = 2048 floats (fits)
#pragma unroll
        for (int j = 0; j < 8; j++) red[ty * 128 + tx * 8 + j] = colsum[j];
        __syncthreads();
        if (tid < 128) {
            float s = 0.f;
#pragma unroll
            for (int t = 0; t < 16; t++) s += red[t * 128 + tid];
            atomicAdd(&g_SV[tid], s);
        }
    }
}

// ---------------- per-edge scores: warp/edge, 4 edges per warp --------------
__global__ void __launch_bounds__(256) scores_kernel(
    const void* __restrict__ ei, const float* __restrict__ ea,
    const float* __restrict__ We, const float* __restrict__ be) {
    int warp = threadIdx.x >> 5, lane = threadIdx.x & 31;
    int is64 = g_is64;
    int e0 = (blockIdx.x * 8 + warp) * 4;
#pragma unroll
    for (int u = 0; u < 4; u++) {
        int e = e0 + u;
        int src = edge_val(ei, is64, 0, e);
        int dst = edge_val(ei, is64, 1, e);
        float4 qa = ((const float4*)(g_Q + (size_t)src * NHID))[lane];
        float4 kb = ((const float4*)(g_K + (size_t)dst * NHID))[lane];
        float p = qa.x * kb.x + qa.y * kb.y + qa.z * kb.z + qa.w * kb.w;
        if (lane < EDIM) p += ea[(size_t)e * EDIM + lane] * We[lane];
#pragma unroll
        for (int o = 16; o > 0; o >>= 1) p += __shfl_xor_sync(0xffffffffu, p, o);
        if (lane == 0) {
            float s = p + be[0];
            s = (s >= 0.f) ? s : NSLOPE * s;
            g_escore[e] = s;
            atomicAdd(&g_cnt[src], 1);
        }
    }
}

// ---------------- exclusive scan of degree histogram (single block) ---------
__global__ void __launch_bounds__(1024) scan_kernel() {
    __shared__ int ssum[1024];
    int tid = threadIdx.x;
    int base = tid * 16;
    int loc[16]; int run = 0;
#pragma unroll
    for (int j = 0; j < 16; j++) { loc[j] = run; run += g_cnt[base + j]; }
    ssum[tid] = run;
    __syncthreads();
    int total = run;
    for (int off = 1; off < 1024; off <<= 1) {
        int v = (tid >= off) ? ssum[tid - off] : 0;
        __syncthreads();
        ssum[tid] += v;
        __syncthreads();
    }
    int offset = ssum[tid] - total;
#pragma unroll
    for (int j = 0; j < 16; j++) {
        int v = offset + loc[j];
        g_rowstart[base + j] = v;
        g_cursor[base + j] = v;
    }
    if (tid == 1023) g_rowstart[N_NODES] = NEDGE;
}

// ---------------- CSR scatter of (dst, score) --------------------------------
__global__ void __launch_bounds__(256) scatter_kernel(const void* __restrict__ ei) {
    int e = blockIdx.x * 256 + threadIdx.x;
    int is64 = g_is64;
    int src = edge_val(ei, is64, 0, e);
    int dst = edge_val(ei, is64, 1, e);
    float s = g_escore[e];
    int pos = atomicAdd(&g_cursor[src], 1);
    g_sdst[pos] = dst;
    g_sw[pos] = s;
}

// ---------------- aggregate: block/node stable sparse softmax-matvec --------
// softmax over dense row that is 0 on non-edges:
//   m = max(0, max_group_score); em = exp(-m)
//   coef_g = exp(S_g - m) - em           (per distinct dst group, else 0)
//   x_new  = (em*SV + sum coef_g*V[d]) / (N*em + sum coef_g)
__global__ void __launch_bounds__(128) aggregate_kernel(const float* __restrict__ x) {
    __shared__ int   sd[ROWCAP];
    __shared__ float sw[ROWCAP];
    __shared__ float scoef[ROWCAP];
    __shared__ float warpmax[4];
    int i = blockIdx.x;
    int h = threadIdx.x;
    int beg = g_rowstart[i], end = g_rowstart[i + 1];
    int len = end - beg;
    if (len > ROWCAP) len = ROWCAP;   // unreachable: deg ~ Poisson(32)

    for (int c = h; c < len; c += 128) {
        sd[c] = g_sdst[beg + c];
        sw[c] = g_sw[beg + c];
    }
    __syncthreads();

    // dedup: first occurrence carries the group sum, later duplicates get 0
    float lmax = 0.f;   // includes implicit 0 from non-edge entries
    for (int c = h; c < len; c += 128) {
        int d = sd[c];
        float wsum = 0.f;
        bool first = true;
        for (int j = 0; j < len; j++) {
            if (sd[j] == d) {
                wsum += sw[j];
                if (j < c) first = false;
            }
        }
        lmax = fmaxf(lmax, wsum);
        scoef[c] = first ? wsum : -1e30f;   // sentinel -> coef 0 below
    }
#pragma unroll
    for (int o = 16; o > 0; o >>= 1) lmax = fmaxf(lmax, __shfl_xor_sync(0xffffffffu, lmax, o));
    if ((h & 31) == 0) warpmax[h >> 5] = lmax;
    __syncthreads();
    float m = fmaxf(fmaxf(warpmax[0], warpmax[1]), fmaxf(warpmax[2], warpmax[3]));
    float em = expf(-m);
    __syncthreads();

    for (int c = h; c < len; c += 128) {
        float w = scoef[c];
        scoef[c] = (w > -1e29f) ? (expf(w - m) - em) : 0.f;
    }
    __syncthreads();

    float acc = 0.f, denom = 0.f;
    for (int c = 0; c < len; c++) {
        float cf = scoef[c];
        denom += cf;
        acc = fmaf(cf, g_V[(size_t)sd[c] * NHID + h], acc);
    }
    float val = x[(size_t)i * NHID + h]
              + (acc + em * g_SV[h]) / (em * (float)N_NODES + denom);
    g_h1[(size_t)i * NHID + h] = val;
}

// ---------------- BN1 stats --------------------------------------------------
__global__ void __launch_bounds__(128) stats1_kernel() {
    int h = threadIdx.x;
    size_t r0 = (size_t)blockIdx.x * 256;
    float a = 0.f, b = 0.f;
    for (int r = 0; r < 256; r++) {
        float v = g_h1[(r0 + r) * NHID + h];
        a += v; b += v * v;
    }
    atomicAdd(&g_s1[h], a);
    atomicAdd(&g_ss1[h], b);
}

// ---------------- FFN GEMM 1: bn1(h1) @ W1 + b1, relu -> mid ----------------
__global__ void __launch_bounds__(256) ffn1_kernel(
    const float* __restrict__ bn1g, const float* __restrict__ bn1b,
    const float* __restrict__ W1, const float* __restrict__ b1) {
    __shared__ float sA[128][33];
    __shared__ float sB[32][128];
    __shared__ float bsc[128], bsh[128];
    int tid = threadIdx.x;
    if (tid < 128) {
        float mu = g_s1[tid] * (1.f / N_NODES);
        float var = g_ss1[tid] * (1.f / N_NODES) - mu * mu;
        float rs = rsqrtf(var + BN_EPS);
        bsc[tid] = bn1g[tid] * rs;
        bsh[tid] = bn1b[tid] - bn1g[tid] * rs * mu;
    }
    __syncthreads();
    int tx = tid & 15, ty = tid >> 4;
    int row0 = blockIdx.x * 128;
    int col0 = blockIdx.y * 128;
    float acc[8][8];
#pragma unroll
    for (int r = 0; r < 8; r++)
#pragma unroll
        for (int j = 0; j < 8; j++) acc[r][j] = 0.f;

    for (int k0 = 0; k0 < NHID; k0 += 32) {
#pragma unroll
        for (int i = tid; i < 1024; i += 256) {
            int r = i >> 3, c = (i & 7) << 2;
            float4 v = *(const float4*)(g_h1 + (size_t)(row0 + r) * NHID + k0 + c);
            sA[r][c]     = fmaf(bsc[k0 + c],     v.x, bsh[k0 + c]);
            sA[r][c + 1] = fmaf(bsc[k0 + c + 1], v.y, bsh[k0 + c + 1]);
            sA[r][c + 2] = fmaf(bsc[k0 + c + 2], v.z, bsh[k0 + c + 2]);
            sA[r][c + 3] = fmaf(bsc[k0 + c + 3], v.w, bsh[k0 + c + 3]);
        }
#pragma unroll
        for (int i = tid; i < 1024; i += 256) {
            int r = i >> 5, c = (i & 31) << 2;
            *(float4*)&sB[r][c] = *(const float4*)(W1 + (size_t)(k0 + r) * NHID2 + col0 + c);
        }
        __syncthreads();
#pragma unroll
        for (int k = 0; k < 32; k++) {
            float a[8], b[8];
#pragma unroll
            for (int r = 0; r < 8; r++) a[r] = sA[ty * 8 + r][k];
            float4 b0 = *(const float4*)&sB[k][tx * 8];
            float4 b1v = *(const float4*)&sB[k][tx * 8 + 4];
            b[0] = b0.x; b[1] = b0.y; b[2] = b0.z; b[3] = b0.w;
            b[4] = b1v.x; b[5] = b1v.y; b[6] = b1v.z; b[7] = b1v.w;
#pragma unroll
            for (int r = 0; r < 8; r++)
#pragma unroll
                for (int j = 0; j < 8; j++) acc[r][j] = fmaf(a[r], b[j], acc[r][j]);
        }
        __syncthreads();
    }
    float bb[8];
#pragma unroll
    for (int j = 0; j < 8; j++) bb[j] = b1[col0 + tx * 8 + j];
#pragma unroll
    for (int r = 0; r < 8; r++) {
        float* o = g_mid + (size_t)(row0 + ty * 8 + r) * NHID2 + col0 + tx * 8;
        float v[8];
#pragma unroll
        for (int j = 0; j < 8; j++) { v[j] = acc[r][j] + bb[j]; v[j] = v[j] > 0.f ? v[j] : 0.f; }
        *(float4*)o = make_float4(v[0], v[1], v[2], v[3]);
        *(float4*)(o + 4) = make_float4(v[4], v[5], v[6], v[7]);
    }
}

// ---------------- FFN GEMM 2: mid @ W2 + b2 + bn1(h1) -> z, fused BN2 stats -
__global__ void __launch_bounds__(256) ffn2_kernel(
    const float* __restrict__ bn1g, const float* __restrict__ bn1b,
    const float* __restrict__ W2, const float* __restrict__ b2) {
    __shared__ float sA[128][33];
    __shared__ float sB[32][128];
    __shared__ float bsc[128], bsh[128];
    int tid = threadIdx.x;
    if (tid < 128) {
        float mu = g_s1[tid] * (1.f / N_NODES);
        float var = g_ss1[tid] * (1.f / N_NODES) - mu * mu;
        float rs = rsqrtf(var + BN_EPS);
        bsc[tid] = bn1g[tid] * rs;
        bsh[tid] = bn1b[tid] - bn1g[tid] * rs * mu;
    }
    __syncthreads();
    int tx = tid & 15, ty = tid >> 4;
    int row0 = blockIdx.x * 128;
    float acc[8][8];
#pragma unroll
    for (int r = 0; r < 8; r++)
#pragma unroll
        for (int j = 0; j < 8; j++) acc[r][j] = 0.f;

    for (int k0 = 0; k0 < NHID2; k0 += 32) {
#pragma unroll
        for (int i = tid; i < 1024; i += 256) {
            int r = i >> 3, c = (i & 7) << 2;
            float4 v = *(const float4*)(g_mid + (size_t)(row0 + r) * NHID2 + k0 + c);
            sA[r][c] = v.x; sA[r][c + 1] = v.y; sA[r][c + 2] = v.z; sA[r][c + 3] = v.w;
        }
#pragma unroll
        for (int i = tid; i < 1024; i += 256) {
            int r = i >> 5, c = (i & 31) << 2;
            *(float4*)&sB[r][c] = *(const float4*)(W2 + (size_t)(k0 + r) * NHID + c);
        }
        __syncthreads();
#pragma unroll
        for (int k = 0; k < 32; k++) {
            float a[8], b[8];
#pragma unroll
            for (int r = 0; r < 8; r++) a[r] = sA[ty * 8 + r][k];
            float4 b0 = *(const float4*)&sB[k][tx * 8];
            float4 b1v = *(const float4*)&sB[k][tx * 8 + 4];
            b[0] = b0.x; b[1] = b0.y; b[2] = b0.z; b[3] = b0.w;
            b[4] = b1v.x; b[5] = b1v.y; b[6] = b1v.z; b[7] = b1v.w;
#pragma unroll
            for (int r = 0; r < 8; r++)
#pragma unroll
                for (int j = 0; j < 8; j++) acc[r][j] = fmaf(a[r], b[j], acc[r][j]);
        }
        __syncthreads();
    }
    float bb[8], sc8[8], sh8[8];
#pragma unroll
    for (int j = 0; j < 8; j++) {
        int c = tx * 8 + j;
        bb[j] = b2[c]; sc8[j] = bsc[c]; sh8[j] = bsh[c];
    }
    float ps[8], psq[8];
#pragma unroll
    for (int j = 0; j < 8; j++) { ps[j] = 0.f; psq[j] = 0.f; }
#pragma unroll
    for (int r = 0; r < 8; r++) {
        size_t base = (size_t)(row0 + ty * 8 + r) * NHID + tx * 8;
        float4 h0 = *(const float4*)(g_h1 + base);
        float4 h1 = *(const float4*)(g_h1 + base + 4);
        float hv[8] = {h0.x, h0.y, h0.z, h0.w, h1.x, h1.y, h1.z, h1.w};
        float v[8];
#pragma unroll
        for (int j = 0; j < 8; j++) {
            v[j] = acc[r][j] + bb[j] + fmaf(sc8[j], hv[j], sh8[j]);
            ps[j] += v[j]; psq[j] += v[j] * v[j];
        }
        *(float4*)(g_z + base) = make_float4(v[0], v[1], v[2], v[3]);
        *(float4*)(g_z + base + 4) = make_float4(v[4], v[5], v[6], v[7]);
    }
    // fused BN2 stats: partials through retired sA (need 4096 <= 4224 floats)
    float* red = &sA[0][0];
#pragma unroll
    for (int j = 0; j < 8; j++) {
        red[ty * 128 + tx * 8 + j] = ps[j];
        red[2048 + ty * 128 + tx * 8 + j] = psq[j];
    }
    __syncthreads();
    if (tid < 128) {
        float s = 0.f, q = 0.f;
#pragma unroll
        for (int t = 0; t < 16; t++) {
            s += red[t * 128 + tid];
            q += red[2048 + t * 128 + tid];
        }
        atomicAdd(&g_s2[tid], s);
        atomicAdd(&g_ss2[tid], q);
    }
}

// ---------------- final: apply BN2 ------------------------------------------
__global__ void __launch_bounds__(256) final_kernel(
    const float* __restrict__ bn2g, const float* __restrict__ bn2b,
    float* __restrict__ out) {
    __shared__ float fsc[128], fsh[128];
    int tid = threadIdx.x;
    if (tid < 128) {
        float mu = g_s2[tid] * (1.f / N_NODES);
        float var = g_ss2[tid] * (1.f / N_NODES) - mu * mu;
        float rs = rsqrtf(var + BN_EPS);
        fsc[tid] = bn2g[tid] * rs;
        fsh[tid] = bn2b[tid] - bn2g[tid] * rs * mu;
    }
    __syncthreads();
    int idx = blockIdx.x * 256 + tid;            // over 524288 float4s
    int col = (idx * 4) & (NHID - 1);
    float4 z = ((const float4*)g_z)[idx];
    float zz[4] = {z.x, z.y, z.z, z.w};
    float o[4];
#pragma unroll
    for (int j = 0; j < 4; j++)
        o[j] = fmaf(fsc[col + j], zz[j], fsh[col + j]);
    ((float4*)out)[idx] = make_float4(o[0], o[1], o[2], o[3]);
}

// ---------------- launch ----------------------------------------------------
extern "C" void kernel_launch(void* const* d_in, const int* in_sizes, int n_in,
                              void* d_out, int out_size) {
    const float* x   = (const float*)d_in[0];
    const void*  ei  = d_in[1];
    const float* ea  = (const float*)d_in[2];
    const float* Wq  = (const float*)d_in[3];
    const float* bq  = (const float*)d_in[4];
    const float* Wk  = (const float*)d_in[5];
    const float* bk  = (const float*)d_in[6];
    const float* Wv  = (const float*)d_in[7];
    const float* bv  = (const float*)d_in[8];
    const float* We  = (const float*)d_in[9];
    const float* be  = (const float*)d_in[10];
    const float* b1g = (const float*)d_in[11];
    const float* b1b = (const float*)d_in[12];
    const float* W1  = (const float*)d_in[13];
    const float* b1  = (const float*)d_in[14];
    const float* W2  = (const float*)d_in[15];
    const float* b2  = (const float*)d_in[16];
    const float* b2g = (const float*)d_in[17];
    const float* b2b = (const float*)d_in[18];
    float* out = (float*)d_out;

    init_kernel<<<64, 256>>>(ei);
    qkv_kernel<<<dim3(128, 3), 256>>>(x, Wq, bq, Wk, bk, Wv, bv);
    scores_kernel<<<16384, 256>>>(ei, ea, We, be);
    scan_kernel<<<1, 1024>>>();
    scatter_kernel<<<2048, 256>>>(ei);
    aggregate_kernel<<<16384, 128>>>(x);
    stats1_kernel<<<64, 128>>>();
    ffn1_kernel<<<dim3(128, 2), 256>>>(b1g, b1b, W1, b1);
    ffn2_kernel<<<128, 256>>>(b1g, b1b, W2, b2);
    final_kernel<<<2048, 256>>>(b2g, b2b, out);
}

// round 5
// speedup vs baseline: 1.1399x; 1.1399x over previous
#include <cuda_runtime.h>

#define N_NODES 16384
#define NHID    128
#define NEDGE   524288
#define EDIM    16
#define NHID2   256
#define BN_EPS  1e-5f
#define NSLOPE  0.01f
#define ROWCAP  256

// ---------------- scratch (static __device__ per allocation rules) ----------
static __device__ float g_Q[N_NODES * NHID];
static __device__ float g_K[N_NODES * NHID];
static __device__ float g_V[N_NODES * NHID];
static __device__ float g_SV[NHID];
static __device__ int   g_cnt[N_NODES];
static __device__ int   g_rowstart[N_NODES + 1];
static __device__ int   g_cursor[N_NODES];
static __device__ int   g_bsum[128];
static __device__ int   g_boff[128];
static __device__ int   g_sdst[NEDGE];            // CSR dst
static __device__ float g_sw[NEDGE];              // CSR edge bias (ea@We+be)
static __device__ float g_h1[N_NODES * NHID];     // x + x_new (pre-BN1)
static __device__ float g_mid[N_NODES * NHID2];   // relu(bn1(h1)@W1+b1)
static __device__ float g_z[N_NODES * NHID];      // h + ffn (pre-BN2)
static __device__ float g_s1[NHID], g_ss1[NHID], g_s2[NHID], g_ss2[NHID];
static __device__ int   g_is64;

// ---------------- helpers ---------------------------------------------------
__device__ __forceinline__ int edge_val(const void* ei, int is64, int row, int e) {
    if (is64) return (int)((const long long*)ei)[(size_t)row * NEDGE + e];
    return ((const int*)ei)[(size_t)row * NEDGE + e];
}

// ---------------- init: zero accumulators + edge dtype probe ----------------
__global__ void init_kernel(const void* __restrict__ ei) {
    int idx = blockIdx.x * 256 + threadIdx.x;
    if (idx < N_NODES) g_cnt[idx] = 0;
    if (idx < NHID) {
        g_SV[idx] = 0.f;
        g_s1[idx] = 0.f; g_ss1[idx] = 0.f;
        g_s2[idx] = 0.f; g_ss2[idx] = 0.f;
    }
    if (idx == 0) {
        // int64 little-endian: high words of small nonneg values are all 0.
        const int* p = (const int*)ei;
        int nz = 0;
        for (int i = 0; i < 64; i++) nz |= p[2 * i + 1];
        g_is64 = (nz == 0) ? 1 : 0;
    }
}

// ---------------- degree histogram ------------------------------------------
__global__ void __launch_bounds__(256) count_kernel(const void* __restrict__ ei) {
    int e = blockIdx.x * 256 + threadIdx.x;
    int src = edge_val(ei, g_is64, 0, e);
    atomicAdd(&g_cnt[src], 1);
}

// ---------------- 3-phase multi-block exclusive scan ------------------------
__global__ void __launch_bounds__(128) scan1_kernel() {
    __shared__ int s[128];
    int b = blockIdx.x, t = threadIdx.x;
    int v = g_cnt[b * 128 + t];
    s[t] = v;
    __syncthreads();
    for (int off = 1; off < 128; off <<= 1) {
        int u = (t >= off) ? s[t - off] : 0;
        __syncthreads();
        s[t] += u;
        __syncthreads();
    }
    g_rowstart[b * 128 + t] = s[t] - v;   // exclusive within block
    if (t == 127) g_bsum[b] = s[127];
}
__global__ void __launch_bounds__(128) scan2_kernel() {
    __shared__ int s[128];
    int t = threadIdx.x;
    int v = g_bsum[t];
    s[t] = v;
    __syncthreads();
    for (int off = 1; off < 128; off <<= 1) {
        int u = (t >= off) ? s[t - off] : 0;
        __syncthreads();
        s[t] += u;
        __syncthreads();
    }
    g_boff[t] = s[t] - v;
    if (t == 0) g_rowstart[N_NODES] = NEDGE;
}
__global__ void __launch_bounds__(128) scan3_kernel() {
    int b = blockIdx.x, t = threadIdx.x;
    int idx = b * 128 + t;
    int v = g_rowstart[idx] + g_boff[b];
    g_rowstart[idx] = v;
    g_cursor[idx] = v;
}

// ---------------- QKV GEMM: 128x128 tile, 8x8 regs, fp32 --------------------
// V branch additionally reduces per-column sums into g_SV (fused sv_kernel).
__global__ void __launch_bounds__(256) qkv_kernel(
    const float* __restrict__ x,
    const float* __restrict__ Wq, const float* __restrict__ bq,
    const float* __restrict__ Wk, const float* __restrict__ bk,
    const float* __restrict__ Wv, const float* __restrict__ bv) {
    __shared__ float sA[128][33];
    __shared__ float sB[32][128];
    const float* W; const float* bias; float* out;
    if (blockIdx.y == 0)      { W = Wq; bias = bq; out = g_Q; }
    else if (blockIdx.y == 1) { W = Wk; bias = bk; out = g_K; }
    else                      { W = Wv; bias = bv; out = g_V; }

    int tid = threadIdx.x;
    int tx = tid & 15, ty = tid >> 4;
    int row0 = blockIdx.x * 128;

    float acc[8][8];
#pragma unroll
    for (int r = 0; r < 8; r++)
#pragma unroll
        for (int j = 0; j < 8; j++) acc[r][j] = 0.f;

    for (int k0 = 0; k0 < NHID; k0 += 32) {
#pragma unroll
        for (int i = tid; i < 1024; i += 256) {           // A tile 128x32
            int r = i >> 3, c = (i & 7) << 2;
            float4 v = *(const float4*)(x + (size_t)(row0 + r) * NHID + k0 + c);
            sA[r][c] = v.x; sA[r][c + 1] = v.y; sA[r][c + 2] = v.z; sA[r][c + 3] = v.w;
        }
#pragma unroll
        for (int i = tid; i < 1024; i += 256) {           // B tile 32x128
            int r = i >> 5, c = (i & 31) << 2;
            *(float4*)&sB[r][c] = *(const float4*)(W + (size_t)(k0 + r) * NHID + c);
        }
        __syncthreads();
#pragma unroll
        for (int k = 0; k < 32; k++) {
            float a[8], b[8];
#pragma unroll
            for (int r = 0; r < 8; r++) a[r] = sA[ty * 8 + r][k];
            float4 b0 = *(const float4*)&sB[k][tx * 8];
            float4 b1 = *(const float4*)&sB[k][tx * 8 + 4];
            b[0] = b0.x; b[1] = b0.y; b[2] = b0.z; b[3] = b0.w;
            b[4] = b1.x; b[5] = b1.y; b[6] = b1.z; b[7] = b1.w;
#pragma unroll
            for (int r = 0; r < 8; r++)
#pragma unroll
                for (int j = 0; j < 8; j++) acc[r][j] = fmaf(a[r], b[j], acc[r][j]);
        }
        __syncthreads();
    }
    float bb[8];
#pragma unroll
    for (int j = 0; j < 8; j++) bb[j] = bias[tx * 8 + j];
    float colsum[8];
#pragma unroll
    for (int j = 0; j < 8; j++) colsum[j] = 0.f;
#pragma unroll
    for (int r = 0; r < 8; r++) {
        float* o = out + (size_t)(row0 + ty * 8 + r) * NHID + tx * 8;
        float v[8];
#pragma unroll
        for (int j = 0; j < 8; j++) { v[j] = acc[r][j] + bb[j]; colsum[j] += v[j]; }
        *(float4*)o = make_float4(v[0], v[1], v[2], v[3]);
        *(float4*)(o + 4) = make_float4(v[4], v[5], v[6], v[7]);
    }
    if (blockIdx.y == 2) {
        // fused column-sum of V: partials via reused sA, one atomic per column
        float* red = &sA[0][0];                 // 16*128 = 2048 floats (fits)
#pragma unroll
        for (int j = 0; j < 8; j++) red[ty * 128 + tx * 8 + j] = colsum[j];
        __syncthreads();
        if (tid < 128) {
            float s = 0.f;
#pragma unroll
            for (int t = 0; t < 16; t++) s += red[t * 128 + tid];
            atomicAdd(&g_SV[tid], s);
        }
    }
}

// ---------------- CSR scatter of (dst, edge bias) ---------------------------
__global__ void __launch_bounds__(256) scatter_kernel(
    const void* __restrict__ ei, const float* __restrict__ ea,
    const float* __restrict__ We, const float* __restrict__ be) {
    int e = blockIdx.x * 256 + threadIdx.x;
    int is64 = g_is64;
    int src = edge_val(ei, is64, 0, e);
    int dst = edge_val(ei, is64, 1, e);
    const float4* eav = (const float4*)(ea + (size_t)e * EDIM);
    float bias = be[0];
#pragma unroll
    for (int k = 0; k < 4; k++) {
        float4 v = eav[k];
        float4 w = ((const float4*)We)[k];
        bias += v.x * w.x + v.y * w.y + v.z * w.z + v.w * w.w;
    }
    int pos = atomicAdd(&g_cursor[src], 1);
    g_sdst[pos] = dst;
    g_sw[pos] = bias;
}

// ---------------- aggregate: fused score + stable sparse softmax-matvec -----
// Per node i (block): Q[i] loaded once to smem; warps gather K[dst] per edge,
// score s = leaky(Q.K + ebias); dedup duplicate dst (sum scores); stable
// softmax over dense row that is 0 on non-edges:
//   m = max(0, max_group_score); em = exp(-m)
//   coef_g = exp(S_g - m) - em
//   x_new  = (em*SV + sum coef_g*V[d]) / (N*em + sum coef_g)
__global__ void __launch_bounds__(128) aggregate_kernel(const float* __restrict__ x) {
    __shared__ float q[NHID];
    __shared__ int   sd[ROWCAP];
    __shared__ float se[ROWCAP];    // ebias, then coef
    __shared__ float ssc[ROWCAP];   // per-edge leaky score
    __shared__ float warpmax[4];
    int i = blockIdx.x;
    int h = threadIdx.x;
    int lane = h & 31, warp = h >> 5;
    int beg = g_rowstart[i], end = g_rowstart[i + 1];
    int len = end - beg;
    if (len > ROWCAP) len = ROWCAP;   // unreachable: deg ~ Poisson(32)

    q[h] = g_Q[(size_t)i * NHID + h];
    for (int c = h; c < len; c += 128) {
        sd[c] = g_sdst[beg + c];
        se[c] = g_sw[beg + c];
    }
    __syncthreads();

    // score phase: warp-per-edge, K gathered once per edge
    float4 qv = ((const float4*)q)[lane];
    for (int c = warp; c < len; c += 4) {
        float4 kv = ((const float4*)(g_K + (size_t)sd[c] * NHID))[lane];
        float p = qv.x * kv.x + qv.y * kv.y + qv.z * kv.z + qv.w * kv.w;
#pragma unroll
        for (int o = 16; o > 0; o >>= 1) p += __shfl_xor_sync(0xffffffffu, p, o);
        if (lane == 0) {
            float s = p + se[c];
            ssc[c] = (s >= 0.f) ? s : NSLOPE * s;
        }
    }
    __syncthreads();

    // dedup: first occurrence carries the group sum, later duplicates get 0
    float lmax = 0.f;   // includes implicit 0 from non-edge entries
    for (int c = h; c < len; c += 128) {
        int d = sd[c];
        float wsum = 0.f;
        bool first = true;
        for (int j = 0; j < len; j++) {
            if (sd[j] == d) {
                wsum += ssc[j];
                if (j < c) first = false;
            }
        }
        lmax = fmaxf(lmax, wsum);
        se[c] = first ? wsum : -1e30f;   // sentinel -> coef 0 below
    }
#pragma unroll
    for (int o = 16; o > 0; o >>= 1) lmax = fmaxf(lmax, __shfl_xor_sync(0xffffffffu, lmax, o));
    if (lane == 0) warpmax[warp] = lmax;
    __syncthreads();
    float m = fmaxf(fmaxf(warpmax[0], warpmax[1]), fmaxf(warpmax[2], warpmax[3]));
    float em = expf(-m);
    __syncthreads();

    for (int c = h; c < len; c += 128) {
        float w = se[c];
        se[c] = (w > -1e29f) ? (expf(w - m) - em) : 0.f;
    }
    __syncthreads();

    float acc = 0.f, denom = 0.f;
    for (int c = 0; c < len; c++) {
        float cf = se[c];
        denom += cf;
        acc = fmaf(cf, g_V[(size_t)sd[c] * NHID + h], acc);
    }
    float val = x[(size_t)i * NHID + h]
              + (acc + em * g_SV[h]) / (em * (float)N_NODES + denom);
    g_h1[(size_t)i * NHID + h] = val;
}

// ---------------- BN1 stats --------------------------------------------------
__global__ void __launch_bounds__(128) stats1_kernel() {
    int h = threadIdx.x;
    size_t r0 = (size_t)blockIdx.x * 256;
    float a = 0.f, b = 0.f;
    for (int r = 0; r < 256; r++) {
        float v = g_h1[(r0 + r) * NHID + h];
        a += v; b += v * v;
    }
    atomicAdd(&g_s1[h], a);
    atomicAdd(&g_ss1[h], b);
}

// ---------------- FFN GEMM 1: bn1(h1) @ W1 + b1, relu -> mid ----------------
__global__ void __launch_bounds__(256) ffn1_kernel(
    const float* __restrict__ bn1g, const float* __restrict__ bn1b,
    const float* __restrict__ W1, const float* __restrict__ b1) {
    __shared__ float sA[128][33];
    __shared__ float sB[32][128];
    __shared__ float bsc[128], bsh[128];
    int tid = threadIdx.x;
    if (tid < 128) {
        float mu = g_s1[tid] * (1.f / N_NODES);
        float var = g_ss1[tid] * (1.f / N_NODES) - mu * mu;
        float rs = rsqrtf(var + BN_EPS);
        bsc[tid] = bn1g[tid] * rs;
        bsh[tid] = bn1b[tid] - bn1g[tid] * rs * mu;
    }
    __syncthreads();
    int tx = tid & 15, ty = tid >> 4;
    int row0 = blockIdx.x * 128;
    int col0 = blockIdx.y * 128;
    float acc[8][8];
#pragma unroll
    for (int r = 0; r < 8; r++)
#pragma unroll
        for (int j = 0; j < 8; j++) acc[r][j] = 0.f;

    for (int k0 = 0; k0 < NHID; k0 += 32) {
#pragma unroll
        for (int i = tid; i < 1024; i += 256) {
            int r = i >> 3, c = (i & 7) << 2;
            float4 v = *(const float4*)(g_h1 + (size_t)(row0 + r) * NHID + k0 + c);
            sA[r][c]     = fmaf(bsc[k0 + c],     v.x, bsh[k0 + c]);
            sA[r][c + 1] = fmaf(bsc[k0 + c + 1], v.y, bsh[k0 + c + 1]);
            sA[r][c + 2] = fmaf(bsc[k0 + c + 2], v.z, bsh[k0 + c + 2]);
            sA[r][c + 3] = fmaf(bsc[k0 + c + 3], v.w, bsh[k0 + c + 3]);
        }
#pragma unroll
        for (int i = tid; i < 1024; i += 256) {
            int r = i >> 5, c = (i & 31) << 2;
            *(float4*)&sB[r][c] = *(const float4*)(W1 + (size_t)(k0 + r) * NHID2 + col0 + c);
        }
        __syncthreads();
#pragma unroll
        for (int k = 0; k < 32; k++) {
            float a[8], b[8];
#pragma unroll
            for (int r = 0; r < 8; r++) a[r] = sA[ty * 8 + r][k];
            float4 b0 = *(const float4*)&sB[k][tx * 8];
            float4 b1v = *(const float4*)&sB[k][tx * 8 + 4];
            b[0] = b0.x; b[1] = b0.y; b[2] = b0.z; b[3] = b0.w;
            b[4] = b1v.x; b[5] = b1v.y; b[6] = b1v.z; b[7] = b1v.w;
#pragma unroll
            for (int r = 0; r < 8; r++)
#pragma unroll
                for (int j = 0; j < 8; j++) acc[r][j] = fmaf(a[r], b[j], acc[r][j]);
        }
        __syncthreads();
    }
    float bb[8];
#pragma unroll
    for (int j = 0; j < 8; j++) bb[j] = b1[col0 + tx * 8 + j];
#pragma unroll
    for (int r = 0; r < 8; r++) {
        float* o = g_mid + (size_t)(row0 + ty * 8 + r) * NHID2 + col0 + tx * 8;
        float v[8];
#pragma unroll
        for (int j = 0; j < 8; j++) { v[j] = acc[r][j] + bb[j]; v[j] = v[j] > 0.f ? v[j] : 0.f; }
        *(float4*)o = make_float4(v[0], v[1], v[2], v[3]);
        *(float4*)(o + 4) = make_float4(v[4], v[5], v[6], v[7]);
    }
}

// ---------------- FFN GEMM 2: mid @ W2 + b2 + bn1(h1) -> z, fused BN2 stats -
__global__ void __launch_bounds__(256) ffn2_kernel(
    const float* __restrict__ bn1g, const float* __restrict__ bn1b,
    const float* __restrict__ W2, const float* __restrict__ b2) {
    __shared__ float sA[128][33];
    __shared__ float sB[32][128];
    __shared__ float bsc[128], bsh[128];
    int tid = threadIdx.x;
    if (tid < 128) {
        float mu = g_s1[tid] * (1.f / N_NODES);
        float var = g_ss1[tid] * (1.f / N_NODES) - mu * mu;
        float rs = rsqrtf(var + BN_EPS);
        bsc[tid] = bn1g[tid] * rs;
        bsh[tid] = bn1b[tid] - bn1g[tid] * rs * mu;
    }
    __syncthreads();
    int tx = tid & 15, ty = tid >> 4;
    int row0 = blockIdx.x * 128;
    float acc[8][8];
#pragma unroll
    for (int r = 0; r < 8; r++)
#pragma unroll
        for (int j = 0; j < 8; j++) acc[r][j] = 0.f;

    for (int k0 = 0; k0 < NHID2; k0 += 32) {
#pragma unroll
        for (int i = tid; i < 1024; i += 256) {
            int r = i >> 3, c = (i & 7) << 2;
            float4 v = *(const float4*)(g_mid + (size_t)(row0 + r) * NHID2 + k0 + c);
            sA[r][c] = v.x; sA[r][c + 1] = v.y; sA[r][c + 2] = v.z; sA[r][c + 3] = v.w;
        }
#pragma unroll
        for (int i = tid; i < 1024; i += 256) {
            int r = i >> 5, c = (i & 31) << 2;
            *(float4*)&sB[r][c] = *(const float4*)(W2 + (size_t)(k0 + r) * NHID + c);
        }
        __syncthreads();
#pragma unroll
        for (int k = 0; k < 32; k++) {
            float a[8], b[8];
#pragma unroll
            for (int r = 0; r < 8; r++) a[r] = sA[ty * 8 + r][k];
            float4 b0 = *(const float4*)&sB[k][tx * 8];
            float4 b1v = *(const float4*)&sB[k][tx * 8 + 4];
            b[0] = b0.x; b[1] = b0.y; b[2] = b0.z; b[3] = b0.w;
            b[4] = b1v.x; b[5] = b1v.y; b[6] = b1v.z; b[7] = b1v.w;
#pragma unroll
            for (int r = 0; r < 8; r++)
#pragma unroll
                for (int j = 0; j < 8; j++) acc[r][j] = fmaf(a[r], b[j], acc[r][j]);
        }
        __syncthreads();
    }
    float bb[8], sc8[8], sh8[8];
#pragma unroll
    for (int j = 0; j < 8; j++) {
        int c = tx * 8 + j;
        bb[j] = b2[c]; sc8[j] = bsc[c]; sh8[j] = bsh[c];
    }
    float ps[8], psq[8];
#pragma unroll
    for (int j = 0; j < 8; j++) { ps[j] = 0.f; psq[j] = 0.f; }
#pragma unroll
    for (int r = 0; r < 8; r++) {
        size_t base = (size_t)(row0 + ty * 8 + r) * NHID + tx * 8;
        float4 h0 = *(const float4*)(g_h1 + base);
        float4 h1 = *(const float4*)(g_h1 + base + 4);
        float hv[8] = {h0.x, h0.y, h0.z, h0.w, h1.x, h1.y, h1.z, h1.w};
        float v[8];
#pragma unroll
        for (int j = 0; j < 8; j++) {
            v[j] = acc[r][j] + bb[j] + fmaf(sc8[j], hv[j], sh8[j]);
            ps[j] += v[j]; psq[j] += v[j] * v[j];
        }
        *(float4*)(g_z + base) = make_float4(v[0], v[1], v[2], v[3]);
        *(float4*)(g_z + base + 4) = make_float4(v[4], v[5], v[6], v[7]);
    }
    // fused BN2 stats: partials through retired sA (need 4096 <= 4224 floats)
    float* red = &sA[0][0];
#pragma unroll
    for (int j = 0; j < 8; j++) {
        red[ty * 128 + tx * 8 + j] = ps[j];
        red[2048 + ty * 128 + tx * 8 + j] = psq[j];
    }
    __syncthreads();
    if (tid < 128) {
        float s = 0.f, q = 0.f;
#pragma unroll
        for (int t = 0; t < 16; t++) {
            s += red[t * 128 + tid];
            q += red[2048 + t * 128 + tid];
        }
        atomicAdd(&g_s2[tid], s);
        atomicAdd(&g_ss2[tid], q);
    }
}

// ---------------- final: apply BN2 ------------------------------------------
__global__ void __launch_bounds__(256) final_kernel(
    const float* __restrict__ bn2g, const float* __restrict__ bn2b,
    float* __restrict__ out) {
    __shared__ float fsc[128], fsh[128];
    int tid = threadIdx.x;
    if (tid < 128) {
        float mu = g_s2[tid] * (1.f / N_NODES);
        float var = g_ss2[tid] * (1.f / N_NODES) - mu * mu;
        float rs = rsqrtf(var + BN_EPS);
        fsc[tid] = bn2g[tid] * rs;
        fsh[tid] = bn2b[tid] - bn2g[tid] * rs * mu;
    }
    __syncthreads();
    int idx = blockIdx.x * 256 + tid;            // over 524288 float4s
    int col = (idx * 4) & (NHID - 1);
    float4 z = ((const float4*)g_z)[idx];
    float zz[4] = {z.x, z.y, z.z, z.w};
    float o[4];
#pragma unroll
    for (int j = 0; j < 4; j++)
        o[j] = fmaf(fsc[col + j], zz[j], fsh[col + j]);
    ((float4*)out)[idx] = make_float4(o[0], o[1], o[2], o[3]);
}

// ---------------- launch ----------------------------------------------------
extern "C" void kernel_launch(void* const* d_in, const int* in_sizes, int n_in,
                              void* d_out, int out_size) {
    const float* x   = (const float*)d_in[0];
    const void*  ei  = d_in[1];
    const float* ea  = (const float*)d_in[2];
    const float* Wq  = (const float*)d_in[3];
    const float* bq  = (const float*)d_in[4];
    const float* Wk  = (const float*)d_in[5];
    const float* bk  = (const float*)d_in[6];
    const float* Wv  = (const float*)d_in[7];
    const float* bv  = (const float*)d_in[8];
    const float* We  = (const float*)d_in[9];
    const float* be  = (const float*)d_in[10];
    const float* b1g = (const float*)d_in[11];
    const float* b1b = (const float*)d_in[12];
    const float* W1  = (const float*)d_in[13];
    const float* b1  = (const float*)d_in[14];
    const float* W2  = (const float*)d_in[15];
    const float* b2  = (const float*)d_in[16];
    const float* b2g = (const float*)d_in[17];
    const float* b2b = (const float*)d_in[18];
    float* out = (float*)d_out;

    init_kernel<<<64, 256>>>(ei);
    count_kernel<<<2048, 256>>>(ei);
    scan1_kernel<<<128, 128>>>();
    scan2_kernel<<<1, 128>>>();
    scan3_kernel<<<128, 128>>>();
    qkv_kernel<<<dim3(128, 3), 256>>>(x, Wq, bq, Wk, bk, Wv, bv);
    scatter_kernel<<<2048, 256>>>(ei, ea, We, be);
    aggregate_kernel<<<16384, 128>>>(x);
    stats1_kernel<<<64, 128>>>();
    ffn1_kernel<<<dim3(128, 2), 256>>>(b1g, b1b, W1, b1);
    ffn2_kernel<<<128, 256>>>(b1g, b1b, W2, b2);
    final_kernel<<<2048, 256>>>(b2g, b2b, out);
}

// round 7
// speedup vs baseline: 1.2094x; 1.0610x over previous
#include <cuda_runtime.h>

#define N_NODES 16384
#define NHID    128
#define NEDGE   524288
#define EDIM    16
#define NHID2   256
#define BN_EPS  1e-5f
#define NSLOPE  0.01f
#define ROWCAP  256

typedef unsigned long long u64;
typedef unsigned int u32;

// ---------------- scratch (static __device__ per allocation rules) ----------
static __device__ float g_Q[N_NODES * NHID];
static __device__ float g_K[N_NODES * NHID];
static __device__ float g_V[N_NODES * NHID];
static __device__ float g_SV[NHID];
static __device__ int   g_cnt[N_NODES];
static __device__ int   g_rowstart[N_NODES + 1];
static __device__ int   g_cursor[N_NODES];
static __device__ int   g_bsum[128];
static __device__ int   g_sdst[NEDGE];            // CSR dst
static __device__ float g_sw[NEDGE];              // CSR edge bias (ea@We+be)
static __device__ float g_h1[N_NODES * NHID];     // x + x_new (pre-BN1)
static __device__ float g_mid[N_NODES * NHID2];   // relu(bn1(h1)@W1+b1)
static __device__ float g_z[N_NODES * NHID];      // h + ffn (pre-BN2)
static __device__ float g_s1[NHID], g_ss1[NHID], g_s2[NHID], g_ss2[NHID];
static __device__ int   g_is64;

// ---------------- helpers ---------------------------------------------------
__device__ __forceinline__ int edge_val(const void* ei, int is64, int row, int e) {
    if (is64) return (int)((const long long*)ei)[(size_t)row * NEDGE + e];
    return ((const int*)ei)[(size_t)row * NEDGE + e];
}
__device__ __forceinline__ u64 pack2(float lo, float hi) {
    u64 r; asm("mov.b64 %0, {%1,%2};" : "=l"(r) : "f"(lo), "f"(hi)); return r;
}
__device__ __forceinline__ float2 unpack2(u64 v) {
    float2 f; asm("mov.b64 {%0,%1}, %2;" : "=f"(f.x), "=f"(f.y) : "l"(v)); return f;
}
__device__ __forceinline__ void fma2(u64& acc, u64 a, u64 b) {
    asm("fma.rn.f32x2 %0, %1, %2, %0;" : "+l"(acc) : "l"(a), "l"(b));
}
__device__ __forceinline__ float to_tf32(float x) {
    float r; asm("cvt.rna.tf32.f32 %0, %1;" : "=f"(r) : "f"(x)); return r;
}
__device__ __forceinline__ void mma_tf32(float* c, const u32* a, const u32* b) {
    asm volatile(
        "mma.sync.aligned.m16n8k8.row.col.f32.tf32.tf32.f32 "
        "{%0,%1,%2,%3}, {%4,%5,%6,%7}, {%8,%9}, {%0,%1,%2,%3};\n"
        : "+f"(c[0]), "+f"(c[1]), "+f"(c[2]), "+f"(c[3])
        : "r"(a[0]), "r"(a[1]), "r"(a[2]), "r"(a[3]), "r"(b[0]), "r"(b[1]));
}

// ---------------- init: zero accumulators + edge dtype probe ----------------
__global__ void init_kernel(const void* __restrict__ ei) {
    int idx = blockIdx.x * 256 + threadIdx.x;
    if (idx < N_NODES) g_cnt[idx] = 0;
    if (idx < NHID) {
        g_SV[idx] = 0.f;
        g_s1[idx] = 0.f; g_ss1[idx] = 0.f;
        g_s2[idx] = 0.f; g_ss2[idx] = 0.f;
    }
    if (idx == 0) {
        const int* p = (const int*)ei;    // int64 LE: high words of small vals = 0
        int nz = 0;
        for (int i = 0; i < 64; i++) nz |= p[2 * i + 1];
        g_is64 = (nz == 0) ? 1 : 0;
        g_rowstart[N_NODES] = NEDGE;
    }
}

// ---------------- degree histogram ------------------------------------------
__global__ void __launch_bounds__(256) count_kernel(const void* __restrict__ ei) {
    int e = blockIdx.x * 256 + threadIdx.x;
    int src = edge_val(ei, g_is64, 0, e);
    atomicAdd(&g_cnt[src], 1);
}

// ---------------- 2-phase multi-block exclusive scan ------------------------
__global__ void __launch_bounds__(128) scan1_kernel() {
    __shared__ int s[128];
    int b = blockIdx.x, t = threadIdx.x;
    int v = g_cnt[b * 128 + t];
    s[t] = v;
    __syncthreads();
    for (int off = 1; off < 128; off <<= 1) {
        int u = (t >= off) ? s[t - off] : 0;
        __syncthreads();
        s[t] += u;
        __syncthreads();
    }
    g_rowstart[b * 128 + t] = s[t] - v;   // exclusive within block
    if (t == 127) g_bsum[b] = s[127];
}
__global__ void __launch_bounds__(128) scan3_kernel() {
    // every block redundantly scans the 128 block sums (cheap, avoids grid=1)
    __shared__ int s[128];
    int b = blockIdx.x, t = threadIdx.x;
    int v = g_bsum[t];
    s[t] = v;
    __syncthreads();
    for (int off = 1; off < 128; off <<= 1) {
        int u = (t >= off) ? s[t - off] : 0;
        __syncthreads();
        s[t] += u;
        __syncthreads();
    }
    int boff = s[b] - g_bsum[b];          // exclusive prefix for this block
    int idx = b * 128 + t;
    int val = g_rowstart[idx] + boff;
    g_rowstart[idx] = val;
    g_cursor[idx] = val;
}

// ---------------- QKV GEMM: 128x128 tile, 8x8 regs, packed f32x2 FFMA -------
// Exact fp32 semantics (fma.rn per half), 2x fma-pipe throughput.
// V branch additionally reduces per-column sums into g_SV.
__global__ void __launch_bounds__(256) qkv_kernel(
    const float* __restrict__ x,
    const float* __restrict__ Wq, const float* __restrict__ bq,
    const float* __restrict__ Wk, const float* __restrict__ bk,
    const float* __restrict__ Wv, const float* __restrict__ bv) {
    __shared__ float sA[128][33];
    __shared__ float sB[32][128];
    const float* W; const float* bias; float* out;
    if (blockIdx.y == 0)      { W = Wq; bias = bq; out = g_Q; }
    else if (blockIdx.y == 1) { W = Wk; bias = bk; out = g_K; }
    else                      { W = Wv; bias = bv; out = g_V; }

    int tid = threadIdx.x;
    int tx = tid & 15, ty = tid >> 4;
    int row0 = blockIdx.x * 128;

    u64 acc2[8][4];
    u64 z2 = pack2(0.f, 0.f);
#pragma unroll
    for (int r = 0; r < 8; r++)
#pragma unroll
        for (int j = 0; j < 4; j++) acc2[r][j] = z2;

    for (int k0 = 0; k0 < NHID; k0 += 32) {
#pragma unroll
        for (int i = tid; i < 1024; i += 256) {           // A tile 128x32
            int r = i >> 3, c = (i & 7) << 2;
            float4 v = *(const float4*)(x + (size_t)(row0 + r) * NHID + k0 + c);
            sA[r][c] = v.x; sA[r][c + 1] = v.y; sA[r][c + 2] = v.z; sA[r][c + 3] = v.w;
        }
#pragma unroll
        for (int i = tid; i < 1024; i += 256) {           // B tile 32x128
            int r = i >> 5, c = (i & 31) << 2;
            *(float4*)&sB[r][c] = *(const float4*)(W + (size_t)(k0 + r) * NHID + c);
        }
        __syncthreads();
#pragma unroll
        for (int k = 0; k < 32; k++) {
            float4 b0 = *(const float4*)&sB[k][tx * 8];
            float4 b1 = *(const float4*)&sB[k][tx * 8 + 4];
            u64 bp[4];
            bp[0] = pack2(b0.x, b0.y); bp[1] = pack2(b0.z, b0.w);
            bp[2] = pack2(b1.x, b1.y); bp[3] = pack2(b1.z, b1.w);
#pragma unroll
            for (int r = 0; r < 8; r++) {
                float av = sA[ty * 8 + r][k];
                u64 ap = pack2(av, av);
#pragma unroll
                for (int j = 0; j < 4; j++) fma2(acc2[r][j], ap, bp[j]);
            }
        }
        __syncthreads();
    }
    float bb[8];
#pragma unroll
    for (int j = 0; j < 8; j++) bb[j] = bias[tx * 8 + j];
    float colsum[8];
#pragma unroll
    for (int j = 0; j < 8; j++) colsum[j] = 0.f;
#pragma unroll
    for (int r = 0; r < 8; r++) {
        float* o = out + (size_t)(row0 + ty * 8 + r) * NHID + tx * 8;
        float v[8];
#pragma unroll
        for (int j = 0; j < 4; j++) {
            float2 p = unpack2(acc2[r][j]);
            v[2 * j] = p.x + bb[2 * j];
            v[2 * j + 1] = p.y + bb[2 * j + 1];
        }
#pragma unroll
        for (int j = 0; j < 8; j++) colsum[j] += v[j];
        *(float4*)o = make_float4(v[0], v[1], v[2], v[3]);
        *(float4*)(o + 4) = make_float4(v[4], v[5], v[6], v[7]);
    }
    if (blockIdx.y == 2) {
        float* red = &sA[0][0];                 // 16*128 = 2048 floats (fits)
#pragma unroll
        for (int j = 0; j < 8; j++) red[ty * 128 + tx * 8 + j] = colsum[j];
        __syncthreads();
        if (tid < 128) {
            float s = 0.f;
#pragma unroll
            for (int t = 0; t < 16; t++) s += red[t * 128 + tid];
            atomicAdd(&g_SV[tid], s);
        }
    }
}

// ---------------- CSR scatter of (dst, edge bias) ---------------------------
__global__ void __launch_bounds__(256) scatter_kernel(
    const void* __restrict__ ei, const float* __restrict__ ea,
    const float* __restrict__ We, const float* __restrict__ be) {
    int e = blockIdx.x * 256 + threadIdx.x;
    int is64 = g_is64;
    int src = edge_val(ei, is64, 0, e);
    int dst = edge_val(ei, is64, 1, e);
    const float4* eav = (const float4*)(ea + (size_t)e * EDIM);
    float bias = be[0];
#pragma unroll
    for (int k = 0; k < 4; k++) {
        float4 v = eav[k];
        float4 w = ((const float4*)We)[k];
        bias += v.x * w.x + v.y * w.y + v.z * w.z + v.w * w.w;
    }
    int pos = atomicAdd(&g_cursor[src], 1);
    g_sdst[pos] = dst;
    g_sw[pos] = bias;
}

// ---------------- aggregate: fused score + stable sparse softmax-matvec -----
__global__ void __launch_bounds__(128) aggregate_kernel(const float* __restrict__ x) {
    __shared__ float q[NHID];
    __shared__ int   sd[ROWCAP];
    __shared__ float se[ROWCAP];    // ebias, then coef
    __shared__ float ssc[ROWCAP];   // per-edge leaky score
    __shared__ float warpmax[4];
    int i = blockIdx.x;
    int h = threadIdx.x;
    int lane = h & 31, warp = h >> 5;
    int beg = g_rowstart[i], end = g_rowstart[i + 1];
    int len = end - beg;
    if (len > ROWCAP) len = ROWCAP;   // unreachable: deg ~ Poisson(32)

    q[h] = g_Q[(size_t)i * NHID + h];
    for (int c = h; c < len; c += 128) {
        sd[c] = g_sdst[beg + c];
        se[c] = g_sw[beg + c];
    }
    __syncthreads();

    float4 qv = ((const float4*)q)[lane];
    for (int c = warp; c < len; c += 4) {
        float4 kv = ((const float4*)(g_K + (size_t)sd[c] * NHID))[lane];
        float p = qv.x * kv.x + qv.y * kv.y + qv.z * kv.z + qv.w * kv.w;
#pragma unroll
        for (int o = 16; o > 0; o >>= 1) p += __shfl_xor_sync(0xffffffffu, p, o);
        if (lane == 0) {
            float s = p + se[c];
            ssc[c] = (s >= 0.f) ? s : NSLOPE * s;
        }
    }
    __syncthreads();

    float lmax = 0.f;   // includes implicit 0 from non-edge entries
    for (int c = h; c < len; c += 128) {
        int d = sd[c];
        float wsum = 0.f;
        bool first = true;
        for (int j = 0; j < len; j++) {
            if (sd[j] == d) {
                wsum += ssc[j];
                if (j < c) first = false;
            }
        }
        lmax = fmaxf(lmax, wsum);
        se[c] = first ? wsum : -1e30f;
    }
#pragma unroll
    for (int o = 16; o > 0; o >>= 1) lmax = fmaxf(lmax, __shfl_xor_sync(0xffffffffu, lmax, o));
    if (lane == 0) warpmax[warp] = lmax;
    __syncthreads();
    float m = fmaxf(fmaxf(warpmax[0], warpmax[1]), fmaxf(warpmax[2], warpmax[3]));
    float em = expf(-m);
    __syncthreads();

    for (int c = h; c < len; c += 128) {
        float w = se[c];
        se[c] = (w > -1e29f) ? (expf(w - m) - em) : 0.f;
    }
    __syncthreads();

    float acc = 0.f, denom = 0.f;
    for (int c = 0; c < len; c++) {
        float cf = se[c];
        denom += cf;
        acc = fmaf(cf, g_V[(size_t)sd[c] * NHID + h], acc);
    }
    float val = x[(size_t)i * NHID + h]
              + (acc + em * g_SV[h]) / (em * (float)N_NODES + denom);
    g_h1[(size_t)i * NHID + h] = val;
}

// ---------------- BN stats (shared shape) ------------------------------------
__global__ void __launch_bounds__(128) stats1_kernel() {
    int h = threadIdx.x;
    size_t r0 = (size_t)blockIdx.x * 256;
    float a = 0.f, b = 0.f;
    for (int r = 0; r < 256; r++) {
        float v = g_h1[(r0 + r) * NHID + h];
        a += v; b += v * v;
    }
    atomicAdd(&g_s1[h], a);
    atomicAdd(&g_ss1[h], b);
}
__global__ void __launch_bounds__(128) stats2_kernel() {
    int h = threadIdx.x;
    size_t r0 = (size_t)blockIdx.x * 256;
    float a = 0.f, b = 0.f;
    for (int r = 0; r < 256; r++) {
        float v = g_z[(r0 + r) * NHID + h];
        a += v; b += v * v;
    }
    atomicAdd(&g_s2[h], a);
    atomicAdd(&g_ss2[h], b);
}

// ---------------- FFN GEMM 1: tf32 mma — bn1(h1) @ W1 + b1, relu -> mid -----
// Block tile 128x128, 8 warps as 4(M)x2(N); warp tile 32x64 = 2 m16 x 8 n8.
__global__ void __launch_bounds__(256) ffn1_kernel(
    const float* __restrict__ bn1g, const float* __restrict__ bn1b,
    const float* __restrict__ W1, const float* __restrict__ b1) {
    __shared__ float sA[128][33];
    __shared__ float sB[32][132];
    __shared__ float bsc[128], bsh[128];
    int tid = threadIdx.x;
    int lane = tid & 31, warp = tid >> 5;
    int gid = lane >> 2, tg = lane & 3;
    int warpM = warp & 3, warpN = warp >> 2;
    int row0 = blockIdx.x * 128, col0 = blockIdx.y * 128;

    if (tid < 128) {
        float mu = g_s1[tid] * (1.f / N_NODES);
        float var = g_ss1[tid] * (1.f / N_NODES) - mu * mu;
        float rs = rsqrtf(var + BN_EPS);
        bsc[tid] = bn1g[tid] * rs;
        bsh[tid] = bn1b[tid] - bn1g[tid] * rs * mu;
    }
    __syncthreads();

    float c[2][8][4];
#pragma unroll
    for (int mt = 0; mt < 2; mt++)
#pragma unroll
        for (int nt = 0; nt < 8; nt++)
#pragma unroll
            for (int j = 0; j < 4; j++) c[mt][nt][j] = 0.f;

    for (int k0 = 0; k0 < NHID; k0 += 32) {
#pragma unroll
        for (int i = tid; i < 1024; i += 256) {           // A: bn-apply + tf32
            int r = i >> 3, cc = (i & 7) << 2;
            float4 v = *(const float4*)(g_h1 + (size_t)(row0 + r) * NHID + k0 + cc);
            sA[r][cc]     = to_tf32(fmaf(bsc[k0 + cc],     v.x, bsh[k0 + cc]));
            sA[r][cc + 1] = to_tf32(fmaf(bsc[k0 + cc + 1], v.y, bsh[k0 + cc + 1]));
            sA[r][cc + 2] = to_tf32(fmaf(bsc[k0 + cc + 2], v.z, bsh[k0 + cc + 2]));
            sA[r][cc + 3] = to_tf32(fmaf(bsc[k0 + cc + 3], v.w, bsh[k0 + cc + 3]));
        }
#pragma unroll
        for (int i = tid; i < 1024; i += 256) {           // B: tf32
            int r = i >> 5, cc = (i & 31) << 2;
            float4 v = *(const float4*)(W1 + (size_t)(k0 + r) * NHID2 + col0 + cc);
            sB[r][cc] = to_tf32(v.x); sB[r][cc + 1] = to_tf32(v.y);
            sB[r][cc + 2] = to_tf32(v.z); sB[r][cc + 3] = to_tf32(v.w);
        }
        __syncthreads();
#pragma unroll
        for (int ks = 0; ks < 4; ks++) {
            u32 a[2][4], b[8][2];
#pragma unroll
            for (int mt = 0; mt < 2; mt++) {
                int ar = warpM * 32 + mt * 16 + gid;
                int kc = ks * 8 + tg;
                a[mt][0] = __float_as_uint(sA[ar][kc]);
                a[mt][1] = __float_as_uint(sA[ar + 8][kc]);
                a[mt][2] = __float_as_uint(sA[ar][kc + 4]);
                a[mt][3] = __float_as_uint(sA[ar + 8][kc + 4]);
            }
#pragma unroll
            for (int nt = 0; nt < 8; nt++) {
                int bc = warpN * 64 + nt * 8 + gid;
                int kc = ks * 8 + tg;
                b[nt][0] = __float_as_uint(sB[kc][bc]);
                b[nt][1] = __float_as_uint(sB[kc + 4][bc]);
            }
#pragma unroll
            for (int mt = 0; mt < 2; mt++)
#pragma unroll
                for (int nt = 0; nt < 8; nt++)
                    mma_tf32(c[mt][nt], a[mt], b[nt]);
        }
        __syncthreads();
    }
    // epilogue: +bias, relu, store float2 pairs
#pragma unroll
    for (int mt = 0; mt < 2; mt++) {
        int r0 = row0 + warpM * 32 + mt * 16 + gid;
#pragma unroll
        for (int nt = 0; nt < 8; nt++) {
            int cc = col0 + warpN * 64 + nt * 8 + 2 * tg;
            float bb0 = b1[cc], bb1 = b1[cc + 1];
            float v0 = fmaxf(c[mt][nt][0] + bb0, 0.f);
            float v1 = fmaxf(c[mt][nt][1] + bb1, 0.f);
            float v2 = fmaxf(c[mt][nt][2] + bb0, 0.f);
            float v3 = fmaxf(c[mt][nt][3] + bb1, 0.f);
            *(float2*)(g_mid + (size_t)r0 * NHID2 + cc) = make_float2(v0, v1);
            *(float2*)(g_mid + (size_t)(r0 + 8) * NHID2 + cc) = make_float2(v2, v3);
        }
    }
}

// ---------------- FFN GEMM 2: tf32 mma — mid @ W2 + b2 + bn1(h1) -> z -------
__global__ void __launch_bounds__(256) ffn2_kernel(
    const float* __restrict__ bn1g, const float* __restrict__ bn1b,
    const float* __restrict__ W2, const float* __restrict__ b2) {
    __shared__ float sA[128][33];
    __shared__ float sB[32][132];
    __shared__ float bsc[128], bsh[128];
    int tid = threadIdx.x;
    int lane = tid & 31, warp = tid >> 5;
    int gid = lane >> 2, tg = lane & 3;
    int warpM = warp & 3, warpN = warp >> 2;
    int row0 = blockIdx.x * 128;

    if (tid < 128) {
        float mu = g_s1[tid] * (1.f / N_NODES);
        float var = g_ss1[tid] * (1.f / N_NODES) - mu * mu;
        float rs = rsqrtf(var + BN_EPS);
        bsc[tid] = bn1g[tid] * rs;
        bsh[tid] = bn1b[tid] - bn1g[tid] * rs * mu;
    }
    __syncthreads();

    float c[2][8][4];
#pragma unroll
    for (int mt = 0; mt < 2; mt++)
#pragma unroll
        for (int nt = 0; nt < 8; nt++)
#pragma unroll
            for (int j = 0; j < 4; j++) c[mt][nt][j] = 0.f;

    for (int k0 = 0; k0 < NHID2; k0 += 32) {
#pragma unroll
        for (int i = tid; i < 1024; i += 256) {
            int r = i >> 3, cc = (i & 7) << 2;
            float4 v = *(const float4*)(g_mid + (size_t)(row0 + r) * NHID2 + k0 + cc);
            sA[r][cc] = to_tf32(v.x); sA[r][cc + 1] = to_tf32(v.y);
            sA[r][cc + 2] = to_tf32(v.z); sA[r][cc + 3] = to_tf32(v.w);
        }
#pragma unroll
        for (int i = tid; i < 1024; i += 256) {
            int r = i >> 5, cc = (i & 31) << 2;
            float4 v = *(const float4*)(W2 + (size_t)(k0 + r) * NHID + cc);
            sB[r][cc] = to_tf32(v.x); sB[r][cc + 1] = to_tf32(v.y);
            sB[r][cc + 2] = to_tf32(v.z); sB[r][cc + 3] = to_tf32(v.w);
        }
        __syncthreads();
#pragma unroll
        for (int ks = 0; ks < 4; ks++) {
            u32 a[2][4], b[8][2];
#pragma unroll
            for (int mt = 0; mt < 2; mt++) {
                int ar = warpM * 32 + mt * 16 + gid;
                int kc = ks * 8 + tg;
                a[mt][0] = __float_as_uint(sA[ar][kc]);
                a[mt][1] = __float_as_uint(sA[ar + 8][kc]);
                a[mt][2] = __float_as_uint(sA[ar][kc + 4]);
                a[mt][3] = __float_as_uint(sA[ar + 8][kc + 4]);
            }
#pragma unroll
            for (int nt = 0; nt < 8; nt++) {
                int bc = warpN * 64 + nt * 8 + gid;
                int kc = ks * 8 + tg;
                b[nt][0] = __float_as_uint(sB[kc][bc]);
                b[nt][1] = __float_as_uint(sB[kc + 4][bc]);
            }
#pragma unroll
            for (int mt = 0; mt < 2; mt++)
#pragma unroll
                for (int nt = 0; nt < 8; nt++)
                    mma_tf32(c[mt][nt], a[mt], b[nt]);
        }
        __syncthreads();
    }
    // epilogue: + b2 + bn1(h1) residual, store z
#pragma unroll
    for (int mt = 0; mt < 2; mt++) {
        int r0 = row0 + warpM * 32 + mt * 16 + gid;
#pragma unroll
        for (int nt = 0; nt < 8; nt++) {
            int cc = warpN * 64 + nt * 8 + 2 * tg;
            float bb0 = b2[cc], bb1 = b2[cc + 1];
            float s0 = bsc[cc], s1 = bsc[cc + 1];
            float t0 = bsh[cc], t1 = bsh[cc + 1];
            float2 hA = *(const float2*)(g_h1 + (size_t)r0 * NHID + cc);
            float2 hB = *(const float2*)(g_h1 + (size_t)(r0 + 8) * NHID + cc);
            float v0 = c[mt][nt][0] + bb0 + fmaf(s0, hA.x, t0);
            float v1 = c[mt][nt][1] + bb1 + fmaf(s1, hA.y, t1);
            float v2 = c[mt][nt][2] + bb0 + fmaf(s0, hB.x, t0);
            float v3 = c[mt][nt][3] + bb1 + fmaf(s1, hB.y, t1);
            *(float2*)(g_z + (size_t)r0 * NHID + cc) = make_float2(v0, v1);
            *(float2*)(g_z + (size_t)(r0 + 8) * NHID + cc) = make_float2(v2, v3);
        }
    }
}

// ---------------- final: apply BN2 ------------------------------------------
__global__ void __launch_bounds__(256) final_kernel(
    const float* __restrict__ bn2g, const float* __restrict__ bn2b,
    float* __restrict__ out) {
    __shared__ float fsc[128], fsh[128];
    int tid = threadIdx.x;
    if (tid < 128) {
        float mu = g_s2[tid] * (1.f / N_NODES);
        float var = g_ss2[tid] * (1.f / N_NODES) - mu * mu;
        float rs = rsqrtf(var + BN_EPS);
        fsc[tid] = bn2g[tid] * rs;
        fsh[tid] = bn2b[tid] - bn2g[tid] * rs * mu;
    }
    __syncthreads();
    int idx = blockIdx.x * 256 + tid;            // over 524288 float4s
    int col = (idx * 4) & (NHID - 1);
    float4 z = ((const float4*)g_z)[idx];
    float zz[4] = {z.x, z.y, z.z, z.w};
    float o[4];
#pragma unroll
    for (int j = 0; j < 4; j++)
        o[j] = fmaf(fsc[col + j], zz[j], fsh[col + j]);
    ((float4*)out)[idx] = make_float4(o[0], o[1], o[2], o[3]);
}

// ---------------- launch ----------------------------------------------------
extern "C" void kernel_launch(void* const* d_in, const int* in_sizes, int n_in,
                              void* d_out, int out_size) {
    const float* x   = (const float*)d_in[0];
    const void*  ei  = d_in[1];
    const float* ea  = (const float*)d_in[2];
    const float* Wq  = (const float*)d_in[3];
    const float* bq  = (const float*)d_in[4];
    const float* Wk  = (const float*)d_in[5];
    const float* bk  = (const float*)d_in[6];
    const float* Wv  = (const float*)d_in[7];
    const float* bv  = (const float*)d_in[8];
    const float* We  = (const float*)d_in[9];
    const float* be  = (const float*)d_in[10];
    const float* b1g = (const float*)d_in[11];
    const float* b1b = (const float*)d_in[12];
    const float* W1  = (const float*)d_in[13];
    const float* b1  = (const float*)d_in[14];
    const float* W2  = (const float*)d_in[15];
    const float* b2  = (const float*)d_in[16];
    const float* b2g = (const float*)d_in[17];
    const float* b2b = (const float*)d_in[18];
    float* out = (float*)d_out;

    init_kernel<<<64, 256>>>(ei);
    count_kernel<<<2048, 256>>>(ei);
    scan1_kernel<<<128, 128>>>();
    scan3_kernel<<<128, 128>>>();
    qkv_kernel<<<dim3(128, 3), 256>>>(x, Wq, bq, Wk, bk, Wv, bv);
    scatter_kernel<<<2048, 256>>>(ei, ea, We, be);
    aggregate_kernel<<<16384, 128>>>(x);
    stats1_kernel<<<64, 128>>>();
    ffn1_kernel<<<dim3(128, 2), 256>>>(b1g, b1b, W1, b1);
    ffn2_kernel<<<128, 256>>>(b1g, b1b, W2, b2);
    stats2_kernel<<<64, 128>>>();
    final_kernel<<<2048, 256>>>(b2g, b2b, out);
}